// round 13
// baseline (speedup 1.0000x reference)
#include <cuda_runtime.h>
#include <cuda_fp16.h>
#include <cstdint>

#define B_TOK 65536
#define KD    512
#define NC    101
#define NE    8
#define NH    256
#define N1    2048

#define BM      64
#define THREADS 256

// strides in halves (padded for conflict-free ldmatrix)
#define B_ST  72     // 144 B rows (64-half slab + 8 pad)
#define H_ST  136    // 272 B rows (128-col half-tile + 8 pad)

// ---------------- device scratch ----------------
__device__ __half g_Xh [B_TOK * KD];   // X in fp16 (64 MB)
__device__ __half g_W1T[N1 * KD];      // [n=e*256+h][d] fp16
__device__ __half g_W2T[128 * N1];     // [c(pad128)][e*256+h] fp16
__device__ float  g_G  [B_TOK * NE];   // gates fp32

// ---------------- helpers ----------------
__device__ __forceinline__ uint32_t smem_u32(const void* p) {
    uint32_t a;
    asm("{ .reg .u64 t; cvta.to.shared.u64 t, %1; cvt.u32.u64 %0, t; }" : "=r"(a) : "l"(p));
    return a;
}
__device__ __forceinline__ void cpa16(uint32_t s, const void* g) {
    asm volatile("cp.async.cg.shared.global [%0], [%1], 16;" :: "r"(s), "l"(g));
}
#define CP_COMMIT() asm volatile("cp.async.commit_group;" ::: "memory")
#define CP_WAIT0()  asm volatile("cp.async.wait_group 0;" ::: "memory")
#define CP_WAIT1()  asm volatile("cp.async.wait_group 1;" ::: "memory")

__device__ __forceinline__ void ldm4(uint32_t* r, uint32_t addr) {
    asm volatile("ldmatrix.sync.aligned.m8n8.x4.shared.b16 {%0,%1,%2,%3}, [%4];"
                 : "=r"(r[0]), "=r"(r[1]), "=r"(r[2]), "=r"(r[3]) : "r"(addr));
}
__device__ __forceinline__ void mma_f16(float* d, const uint32_t* a, const uint32_t* b) {
    asm volatile(
        "mma.sync.aligned.m16n8k16.row.col.f32.f16.f16.f32 "
        "{%0,%1,%2,%3}, {%4,%5,%6,%7}, {%8,%9}, {%0,%1,%2,%3};"
        : "+f"(d[0]), "+f"(d[1]), "+f"(d[2]), "+f"(d[3])
        : "r"(a[0]), "r"(a[1]), "r"(a[2]), "r"(a[3]), "r"(b[0]), "r"(b[1]));
}

// ---------------- prep kernels ----------------
__global__ void k_tw1(const float* __restrict__ W1) {
    // W1 [E][D][H] fp32 -> g_W1T[e*NH+h][d] fp16
    __shared__ float tile[32][33];
    int e = blockIdx.z, d0 = blockIdx.y * 32, h0 = blockIdx.x * 32;
    int tx = threadIdx.x, ty = threadIdx.y;
    #pragma unroll
    for (int r = 0; r < 32; r += 8)
        tile[ty + r][tx] = W1[((size_t)e * KD + d0 + ty + r) * NH + h0 + tx];
    __syncthreads();
    #pragma unroll
    for (int r = 0; r < 32; r += 8)
        g_W1T[((size_t)e * NH + h0 + ty + r) * KD + d0 + tx] =
            __float2half_rn(tile[tx][ty + r]);
}

__global__ void k_tw2(const float* __restrict__ W2) {
    // W2 [E][H][C] -> g_W2T[c][e*256+h] fp16, c padded to 128
    int idx = blockIdx.x * 256 + threadIdx.x;    // over 128*2048
    int eh = idx & (N1 - 1);
    int c  = idx >> 11;
    g_W2T[(size_t)c * N1 + eh] =
        (c < NC) ? __float2half_rn(W2[(size_t)eh * NC + c]) : __half(0.0f);
}

__global__ void k_gates(const float* __restrict__ X, const float* __restrict__ Wg,
                        const float* __restrict__ bg) {
    // 8 rows per 256-thread block; Wg staged transposed in smem (conflict-free)
    __shared__ float wgs[NE][KD];
    __shared__ float bgs[NE];
    int tid = threadIdx.x;
    for (int i = tid; i < KD * NE; i += THREADS) {
        int d = i >> 3, e = i & 7;
        wgs[e][d] = Wg[i];
    }
    if (tid < NE) bgs[tid] = bg[tid];
    __syncthreads();

    int wid = tid >> 5, lane = tid & 31;
    int row = blockIdx.x * 8 + wid;
    const float4* xr = reinterpret_cast<const float4*>(X + (size_t)row * KD);
    __half2* xh = reinterpret_cast<__half2*>(g_Xh + (size_t)row * KD);

    float a[NE];
    #pragma unroll
    for (int e = 0; e < NE; e++) a[e] = 0.f;
    #pragma unroll
    for (int i = 0; i < 4; i++) {
        int d4 = lane + i * 32;          // float4 index; d = 4*d4
        float4 xv = xr[d4];
        xh[d4 * 2]     = __floats2half2_rn(xv.x, xv.y);
        xh[d4 * 2 + 1] = __floats2half2_rn(xv.z, xv.w);
        int d = d4 * 4;
        #pragma unroll
        for (int e = 0; e < NE; e++) {
            float4 w = *reinterpret_cast<const float4*>(&wgs[e][d]);
            a[e] += xv.x * w.x + xv.y * w.y + xv.z * w.z + xv.w * w.w;
        }
    }
    #pragma unroll
    for (int e = 0; e < NE; e++)
        #pragma unroll
        for (int off = 16; off > 0; off >>= 1)
            a[e] += __shfl_xor_sync(0xFFFFFFFFu, a[e], off);
    if (lane == 0) {
        float m = -1e30f;
        #pragma unroll
        for (int e = 0; e < NE; e++) { a[e] += bgs[e]; m = fmaxf(m, a[e]); }
        float s = 0.f;
        #pragma unroll
        for (int e = 0; e < NE; e++) { a[e] = __expf(a[e] - m); s += a[e]; }
        float inv = 1.0f / s;
        #pragma unroll
        for (int e = 0; e < NE; e++) g_G[(size_t)row * NE + e] = a[e] * inv;
    }
}

// ---------------- smem layout (bytes), per CTA = 110592 (2 CTAs/SM) ----------------
#define A_SLAB  (64 * B_ST * 2)          // 9216
#define B_SLAB  (128 * B_ST * 2)         // 18432
#define OFF_AS  0
#define OFF_BS  (3 * A_SLAB)             // 27648
#define OFF_HS  (OFF_BS + 3 * B_SLAB)    // 82944
#define OFF_B1  (OFF_HS + 64 * H_ST * 2) // 100352
#define OFF_B2  (OFF_B1 + N1 * 2)        // 104448
#define OFF_GS  (OFF_B2 + 128 * NE * 4)  // 108544
#define SM_TOT  (OFF_GS + 64 * NE * 4)   // 110592

__device__ __forceinline__ void ld_slabA(uint32_t dst, const __half* src, int tid) {
    #pragma unroll
    for (int it = 0; it < 2; it++) {
        int id = tid + it * THREADS;      // 0..511
        int r = id >> 3, j = id & 7;
        cpa16(dst + (uint32_t)(r * (B_ST * 2) + j * 16),
              src + (size_t)r * KD + j * 8);
    }
}
__device__ __forceinline__ void ld_slabB(uint32_t dst, const __half* src,
                                         int stride, int tid) {
    #pragma unroll
    for (int it = 0; it < 4; it++) {
        int id = tid + it * THREADS;      // 0..1023
        int r = id >> 3, j = id & 7;
        cpa16(dst + (uint32_t)(r * (B_ST * 2) + j * 16),
              src + (size_t)r * stride + j * 8);
    }
}

// ---------------- main fused kernel ----------------
__global__ void __launch_bounds__(THREADS, 2)
k_moe(const float* __restrict__ b1, const float* __restrict__ b2,
      float* __restrict__ Out)
{
    extern __shared__ char smem[];
    __half* Hs  = (__half*)(smem + OFF_HS);
    __half* b1h = (__half*)(smem + OFF_B1);
    float*  b2s = (float*)(smem + OFF_B2);
    float*  gs  = (float*)(smem + OFF_GS);

    const int tid  = threadIdx.x;
    const int wid  = tid >> 5, lane = tid & 31;
    const int wm   = wid & 1, wn = wid >> 1;      // 2 x 4 warp grid
    const int m0w  = wm * 32, n0w = wn * 32;
    const int g    = lane >> 2, t = lane & 3;
    const int bm0  = blockIdx.x * BM;

    const uint32_t as_u = smem_u32(smem + OFF_AS);
    const uint32_t bs_u = smem_u32(smem + OFF_BS);
    const uint32_t hs_u = smem_u32(smem + OFF_HS);
    const uint32_t abuf[3] = { as_u, as_u + A_SLAB, as_u + 2 * A_SLAB };
    const uint32_t bbuf[3] = { bs_u, bs_u + B_SLAB, bs_u + 2 * B_SLAB };

    const __half* Xg = g_Xh + (size_t)bm0 * KD;

    // stage biases + gates
    for (int i = tid; i < N1; i += THREADS) b1h[i] = __float2half_rn(b1[i]);
    for (int i = tid; i < 128 * NE; i += THREADS) {
        int cc = i >> 3, e = i & 7;
        b2s[i] = (cc < NC) ? b2[(size_t)e * NC + cc] : 0.0f;
    }
    for (int i = tid; i < BM * NE; i += THREADS) {
        int cc = i >> 3, e = i & 7;
        gs[i] = g_G[(size_t)(bm0 + cc) * NE + e];
    }
    __syncthreads();

    // per-lane ldmatrix address offsets (bytes)
    const uint32_t aoff_a = (uint32_t)((m0w + (lane & 15)) * (B_ST * 2) + (lane >> 4) * 16);
    const uint32_t aoff_h = (uint32_t)((m0w + (lane & 15)) * (H_ST * 2) + (lane >> 4) * 16);
    const uint32_t boff   = (uint32_t)((n0w + ((lane >> 4) << 3) + (lane & 7)) * (B_ST * 2)
                                       + ((lane >> 3) & 1) * 16);

    float acc2[2][4][4];
    #pragma unroll
    for (int i = 0; i < 2; i++)
        #pragma unroll
        for (int j = 0; j < 4; j++)
            #pragma unroll
            for (int q = 0; q < 4; q++) acc2[i][j][q] = 0.0f;

    #pragma unroll 1
    for (int ch = 0; ch < NE; ch++) {
        #pragma unroll 1
        for (int nh = 0; nh < 2; nh++) {
            // ========== GEMM1: acc1 = X @ W1T(half)^T  (K=512, 8 slabs) ==========
            const __half* W1b = g_W1T + (size_t)(ch * NH + nh * 128) * KD;
            ld_slabA(abuf[0], Xg,      tid);
            ld_slabB(bbuf[0], W1b,      KD, tid);
            CP_COMMIT();
            ld_slabA(abuf[1], Xg + 64, tid);
            ld_slabB(bbuf[1], W1b + 64, KD, tid);
            CP_COMMIT();

            float acc1[2][4][4];
            #pragma unroll
            for (int i = 0; i < 2; i++)
                #pragma unroll
                for (int j = 0; j < 4; j++)
                    #pragma unroll
                    for (int q = 0; q < 4; q++) acc1[i][j][q] = 0.0f;

            int st = 0;
            #pragma unroll 1
            for (int kb = 0; kb < 8; kb++) {
                if (kb < 7) { CP_WAIT1(); } else { CP_WAIT0(); }
                __syncthreads();
                if (kb < 6) {
                    int nst = st + 2; if (nst >= 3) nst -= 3;
                    ld_slabA(abuf[nst], Xg  + (kb + 2) * 64, tid);
                    ld_slabB(bbuf[nst], W1b + (kb + 2) * 64, KD, tid);
                    CP_COMMIT();
                }
                const uint32_t ac = abuf[st], bc = bbuf[st];
                #pragma unroll
                for (int kk = 0; kk < 4; kk++) {
                    uint32_t afr[2][4], bfr[2][4];
                    #pragma unroll
                    for (int mf = 0; mf < 2; mf++)
                        ldm4(afr[mf], ac + aoff_a +
                             (uint32_t)(mf * 16 * (B_ST * 2) + kk * 32));
                    #pragma unroll
                    for (int nb = 0; nb < 2; nb++)
                        ldm4(bfr[nb], bc + boff +
                             (uint32_t)(nb * 16 * (B_ST * 2) + kk * 32));
                    #pragma unroll
                    for (int mf = 0; mf < 2; mf++)
                        #pragma unroll
                        for (int nf = 0; nf < 4; nf++)
                            mma_f16(acc1[mf][nf], afr[mf], &bfr[nf >> 1][(nf & 1) * 2]);
                }
                st++; if (st == 3) st = 0;
            }
            __syncthreads();   // all warps done reading G1 stages

            // ========== GEMM2 prologue: load both W2 slabs (hide under epilogue) ==
            const __half* W2b = g_W2T + ch * NH + nh * 128;
            ld_slabB(bbuf[0], W2b,      N1, tid); CP_COMMIT();
            ld_slabB(bbuf[1], W2b + 64, N1, tid); CP_COMMIT();

            // ---- epilogue 1: Hs = fp16(relu(acc1 + b1) * gate) ----
            #pragma unroll
            for (int mf = 0; mf < 2; mf++) {
                int r0 = m0w + mf * 16 + g;
                float g0 = gs[r0 * NE + ch];
                float g1 = gs[(r0 + 8) * NE + ch];
                #pragma unroll
                for (int nf = 0; nf < 4; nf++) {
                    int col = n0w + nf * 8 + 2 * t;
                    const __half* bb = b1h + ch * NH + nh * 128 + col;
                    float b0v = __half2float(bb[0]);
                    float b1v = __half2float(bb[1]);
                    float v00 = fmaxf(acc1[mf][nf][0] + b0v, 0.f) * g0;
                    float v01 = fmaxf(acc1[mf][nf][1] + b1v, 0.f) * g0;
                    float v10 = fmaxf(acc1[mf][nf][2] + b0v, 0.f) * g1;
                    float v11 = fmaxf(acc1[mf][nf][3] + b1v, 0.f) * g1;
                    *reinterpret_cast<__half2*>(Hs + r0 * H_ST + col) =
                        __floats2half2_rn(v00, v01);
                    *reinterpret_cast<__half2*>(Hs + (r0 + 8) * H_ST + col) =
                        __floats2half2_rn(v10, v11);
                }
            }
            __syncthreads();   // Hs visible to all warps

            // ========== GEMM2: acc2 += H(half) @ W2T^T  (K=128, 2 slabs) ==========
            #pragma unroll 1
            for (int kb = 0; kb < 2; kb++) {
                if (kb == 0) { CP_WAIT1(); } else { CP_WAIT0(); }
                __syncthreads();
                const uint32_t bc = bbuf[kb];
                #pragma unroll
                for (int kk = 0; kk < 4; kk++) {
                    uint32_t afr[2][4], bfr[2][4];
                    #pragma unroll
                    for (int mf = 0; mf < 2; mf++)
                        ldm4(afr[mf], hs_u + aoff_h +
                             (uint32_t)(mf * 16 * (H_ST * 2) + kb * 128 + kk * 32));
                    #pragma unroll
                    for (int nb = 0; nb < 2; nb++)
                        ldm4(bfr[nb], bc + boff +
                             (uint32_t)(nb * 16 * (B_ST * 2) + kk * 32));
                    #pragma unroll
                    for (int mf = 0; mf < 2; mf++)
                        #pragma unroll
                        for (int nf = 0; nf < 4; nf++)
                            mma_f16(acc2[mf][nf], afr[mf], &bfr[nf >> 1][(nf & 1) * 2]);
                }
            }
            __syncthreads();   // B ring + Hs free before next body overwrites
        }
    }

    // ================= final epilogue: out = acc2 + G @ b2 =================
    #pragma unroll
    for (int mf = 0; mf < 2; mf++) {
        int r0 = m0w + mf * 16 + g;
        #pragma unroll
        for (int nf = 0; nf < 4; nf++) {
            int col = n0w + nf * 8 + 2 * t;
            #pragma unroll
            for (int q = 0; q < 4; q++) {
                int r  = r0 + ((q >> 1) ? 8 : 0);
                int cc = col + (q & 1);
                if (cc < NC) {
                    float v = acc2[mf][nf][q];
                    const float* gv = gs  + r * NE;
                    const float* bv = b2s + cc * NE;
                    #pragma unroll
                    for (int e = 0; e < NE; e++) v += gv[e] * bv[e];
                    Out[(size_t)(bm0 + r) * NC + cc] = v;
                }
            }
        }
    }
}

// ---------------- launch ----------------
extern "C" void kernel_launch(void* const* d_in, const int* in_sizes, int n_in,
                              void* d_out, int out_size) {
    const float* x  = (const float*)d_in[0];
    const float* W1 = (const float*)d_in[1];
    const float* b1 = (const float*)d_in[2];
    const float* W2 = (const float*)d_in[3];
    const float* b2 = (const float*)d_in[4];
    const float* Wg = (const float*)d_in[5];
    const float* bg = (const float*)d_in[6];
    float* out = (float*)d_out;

    k_tw1  <<<dim3(NH / 32, KD / 32, NE), dim3(32, 8)>>>(W1);
    k_tw2  <<<(128 * N1) / 256, 256>>>(W2);
    k_gates<<<B_TOK / 8, THREADS>>>(x, Wg, bg);

    cudaFuncSetAttribute(k_moe, cudaFuncAttributeMaxDynamicSharedMemorySize, SM_TOT);
    k_moe<<<B_TOK / BM, THREADS, SM_TOT>>>(b1, b2, out);
}